// round 9
// baseline (speedup 1.0000x reference)
#include <cuda_runtime.h>
#include <cstdint>
#include <cstddef>

#define BATCH 1024

__device__ __align__(256) float g_h1[BATCH * 32 * 625];     // (B,32,25,25) planar
__device__ __align__(256) float g_z [BATCH * 169 * 64];     // (B,169,64) pixel-major
__device__ __align__(256) float g_d1[BATCH * 625 * 64];     // (B,625,64) pixel-major
__device__ __align__(256) float g_d2[BATCH * 2500 * 32];    // (B,2500,32) pixel-major
__device__ __align__(256) float g_lsum[2704];
__device__ __align__(256) float g_cnorm[512];

__device__ __forceinline__ void fma4(float4& a, float s, const float4 w) {
    a.x = fmaf(s, w.x, a.x); a.y = fmaf(s, w.y, a.y);
    a.z = fmaf(s, w.z, a.z); a.w = fmaf(s, w.w, a.w);
}

// ---------------- K1: conv1 (1->32, k3 s2 p1, relu), 50->25 -----------------
__global__ void __launch_bounds__(640) k_conv1(const float* __restrict__ x,
                                               const float* __restrict__ w,
                                               const float* __restrict__ bias) {
    __shared__ float ws[288], bs[32];
    int b = blockIdx.x, tid = threadIdx.x;
    if (tid < 288) ws[tid] = w[tid];
    if (tid < 32)  bs[tid] = bias[tid];
    __syncthreads();
    if (tid >= 625) return;
    int oy = tid / 25, ox = tid % 25;
    const float* xb = x + (size_t)b * 2500;
    float xv[9];
#pragma unroll
    for (int ky = 0; ky < 3; ky++)
#pragma unroll
        for (int kx = 0; kx < 3; kx++) {
            int iy = 2 * oy + ky - 1, ix = 2 * ox + kx - 1;
            xv[ky * 3 + kx] = (iy >= 0 && iy < 50 && ix >= 0 && ix < 50) ? xb[iy * 50 + ix] : 0.f;
        }
    float* out = g_h1 + (size_t)b * 20000 + tid;
#pragma unroll
    for (int oc = 0; oc < 32; oc++) {
        float a = bs[oc];
#pragma unroll
        for (int t = 0; t < 9; t++) a = fmaf(xv[t], ws[oc * 9 + t], a);
        out[oc * 625] = fmaxf(a, 0.f);
    }
}

// ------------- K2: conv2 (32->64 k3 s2 p1 relu) + conv3 1x1 -> z ------------
#define ENC23_SMEM ((20000 + 18432 + 4096 + 64 + 64) * 4)
__global__ void __launch_bounds__(192) k_enc23(const float* __restrict__ w2,
                                               const float* __restrict__ b2,
                                               const float* __restrict__ w3,
                                               const float* __restrict__ b3) {
    extern __shared__ float sm[];
    float* h1s = sm;             // 20000 planar; later reused as h2 [169][65]
    float* w2s = sm + 20000;     // [ (t*32+i)*64 + o ]
    float* w3s = sm + 38432;     // [ k*64 + c ]
    float* b2s = sm + 42528;
    float* b3s = sm + 42592;
    int b = blockIdx.x, tid = threadIdx.x;
    const float* h1b = g_h1 + (size_t)b * 20000;
    for (int e = tid; e < 20000; e += 192) h1s[e] = h1b[e];
    for (int e = tid; e < 18432; e += 192) {
        int o = e / 288, r = e % 288, i = r / 9, t = r % 9;
        w2s[(t * 32 + i) * 64 + o] = w2[e];
    }
    for (int e = tid; e < 4096; e += 192) w3s[(e & 63) * 64 + (e >> 6)] = w3[e];
    if (tid < 64) { b2s[tid] = b2[tid]; b3s[tid] = b3[tid]; }
    __syncthreads();

    float4 acc[16];
    if (tid < 169) {
        int oy = tid / 13, ox = tid % 13;
#pragma unroll
        for (int c = 0; c < 16; c++) acc[c] = ((const float4*)b2s)[c];
#pragma unroll 1
        for (int ky = 0; ky < 3; ky++) {
            int iy = 2 * oy + ky - 1;
            if (iy < 0 || iy >= 25) continue;
#pragma unroll 1
            for (int kx = 0; kx < 3; kx++) {
                int ix = 2 * ox + kx - 1;
                if (ix < 0 || ix >= 25) continue;
                const float* hp = h1s + iy * 25 + ix;
                const float4* wp = (const float4*)(w2s + (ky * 3 + kx) * 32 * 64);
#pragma unroll 4
                for (int i = 0; i < 32; i++) {
                    float hv = hp[i * 625];
                    const float4* w4 = wp + i * 16;
#pragma unroll
                    for (int c = 0; c < 16; c++) fma4(acc[c], hv, w4[c]);
                }
            }
        }
    }
    __syncthreads();
    if (tid < 169) {
        float* hrow = h1s + tid * 65;
#pragma unroll
        for (int c = 0; c < 16; c++) {
            hrow[4 * c + 0] = fmaxf(acc[c].x, 0.f); hrow[4 * c + 1] = fmaxf(acc[c].y, 0.f);
            hrow[4 * c + 2] = fmaxf(acc[c].z, 0.f); hrow[4 * c + 3] = fmaxf(acc[c].w, 0.f);
        }
    }
    __syncthreads();
    if (tid < 169) {
        float4 za[16];
#pragma unroll
        for (int c = 0; c < 16; c++) za[c] = ((const float4*)b3s)[c];
        const float* hp = h1s + tid * 65;
#pragma unroll 4
        for (int k = 0; k < 64; k++) {
            float hv = hp[k];
            const float4* w4 = (const float4*)(w3s + k * 64);
#pragma unroll
            for (int c = 0; c < 16; c++) fma4(za[c], hv, w4[c]);
        }
        float4* zp = (float4*)(g_z + ((size_t)b * 169 + tid) * 64);
#pragma unroll
        for (int c = 0; c < 16; c++) zp[c] = za[c];
    }
}

// ---------------- K3a: codebook row norms -----------------------------------
__global__ void k_cnorm(const float* __restrict__ cb) {
    const float* r = cb + threadIdx.x * 64;
    float s = 0.f;
#pragma unroll
    for (int k = 0; k < 64; k++) s = fmaf(r[k], r[k], s);
    g_cnorm[threadIdx.x] = s;
}

// -------- K3: VQ. 64 pixels x 512 codes per block, 8x8 reg tile -------------
#define VQ_SMEM ((4096 + 16448 + 8) * 4)
__global__ void __launch_bounds__(256) k_vq(const float* __restrict__ cb,
                                            float* __restrict__ q) {
    extern __shared__ float sm[];
    float* zs = sm;               // [64][64]
    float* cs = sm + 4096;        // [64][257] k-major padded
    float* sred = sm + 4096 + 16448;
    int tid = threadIdx.x;
    int P0 = blockIdx.x * 64;
    {
        const float4* zsrc = (const float4*)(g_z + (size_t)P0 * 64);
        float4* zd = (float4*)zs;
        for (int e = tid; e < 1024; e += 256) zd[e] = zsrc[e];
    }
    int ty = tid >> 5, tx = tid & 31;
    float bestd[8]; int besti[8];
#pragma unroll
    for (int i = 0; i < 8; i++) { bestd[i] = 3.4e38f; besti[i] = 0; }

    for (int pass = 0; pass < 2; pass++) {
        int C0 = pass * 256;
        __syncthreads();
        for (int e = tid; e < 16384; e += 256) {
            int code = e >> 6, k = e & 63;
            cs[k * 257 + code] = cb[(C0 + code) * 64 + k];
        }
        __syncthreads();
        float dot[8][8];
#pragma unroll
        for (int i = 0; i < 8; i++)
#pragma unroll
            for (int j = 0; j < 8; j++) dot[i][j] = 0.f;
        const float* zrow = zs + (ty * 8) * 64;
#pragma unroll 2
        for (int k = 0; k < 64; k++) {
            float zf[8], cf[8];
#pragma unroll
            for (int i = 0; i < 8; i++) zf[i] = zrow[i * 64 + k];
#pragma unroll
            for (int j = 0; j < 8; j++) cf[j] = cs[k * 257 + tx + 32 * j];
#pragma unroll
            for (int i = 0; i < 8; i++)
#pragma unroll
                for (int j = 0; j < 8; j++) dot[i][j] = fmaf(zf[i], cf[j], dot[i][j]);
        }
#pragma unroll
        for (int j = 0; j < 8; j++) {
            int ci = C0 + tx + 32 * j;
            float cn = __ldg(g_cnorm + ci);
#pragma unroll
            for (int i = 0; i < 8; i++) {
                float d = fmaf(-2.f, dot[i][j], cn);
                if (d < bestd[i]) { bestd[i] = d; besti[i] = ci; }
            }
        }
    }
#pragma unroll
    for (int i = 0; i < 8; i++) {
        float d = bestd[i]; int ci = besti[i];
#pragma unroll
        for (int off = 16; off; off >>= 1) {
            float od = __shfl_xor_sync(0xffffffffu, d, off);
            int   oi = __shfl_xor_sync(0xffffffffu, ci, off);
            if (od < d || (od == d && oi < ci)) { d = od; ci = oi; }
        }
        besti[i] = ci;
    }
    float ls = 0.f;
#pragma unroll
    for (int i = 0; i < 8; i++) {
        int p = ty * 8 + i, ci = besti[i];
        float c0 = __ldg(cb + ci * 64 + tx);
        float c1 = __ldg(cb + ci * 64 + 32 + tx);
        float z0 = zs[p * 64 + tx], z1 = zs[p * 64 + 32 + tx];
        float* qp = q + ((size_t)(P0 + p)) * 64;
        qp[tx] = c0; qp[32 + tx] = c1;
        float d0 = c0 - z0, d1 = c1 - z1;
        ls = fmaf(d0, d0, ls); ls = fmaf(d1, d1, ls);
    }
#pragma unroll
    for (int off = 16; off; off >>= 1) ls += __shfl_xor_sync(0xffffffffu, ls, off);
    if (tx == 0) sred[ty] = ls;
    __syncthreads();
    if (tid == 0) {
        float s = 0.f;
        for (int w = 0; w < 8; w++) s += sred[w];
        g_lsum[blockIdx.x] = s;
    }
}

// loss = 1.25 * sum / (1024*64*169)
__global__ void k_loss(float* __restrict__ out) {
    __shared__ float s[256];
    float a = 0.f;
    for (int e = threadIdx.x; e < 2704; e += 256) a += g_lsum[e];
    s[threadIdx.x] = a;
    __syncthreads();
    for (int st = 128; st; st >>= 1) {
        if (threadIdx.x < st) s[threadIdx.x] += s[threadIdx.x + st];
        __syncthreads();
    }
    if (threadIdx.x == 0) out[0] = s[0] * (1.25f / 11075584.f);
}

// ------- K4: tconv1 (64->64, k3 s2 p1 op0, relu), 13 -> 25, smem-staged -----
// NOTE: weight/bias sections start at 10988 (multiple of 4 floats) so float4
// casts are 16-byte aligned. (10985 in the previous round caused the
// "misaligned address" crash.)
#define T1_SMEM ((10988 + 36864 + 64) * 4)
__global__ void __launch_bounds__(640) k_tconv1(const float* __restrict__ q,
                                                const float* __restrict__ w,
                                                const float* __restrict__ bias) {
    extern __shared__ float sm[];
    float* qs = sm;               // [169][65] (scalar reads only)
    float* ws = sm + 10988;       // [(t*64+i)*64 + o], 16B-aligned
    float* bs = sm + 10988 + 36864;
    int b = blockIdx.x, tid = threadIdx.x;
    const float* qb = q + (size_t)b * 169 * 64;
    for (int e = tid; e < 169 * 64; e += 640) qs[(e >> 6) * 65 + (e & 63)] = qb[e];
    for (int e = tid; e < 36864; e += 640) {
        int o = e / 576, r = e % 576, i = r / 9, t = r % 9;
        ws[(t * 64 + i) * 64 + o] = w[e];
    }
    if (tid < 64) bs[tid] = bias[tid];
    __syncthreads();
    if (tid >= 625) return;
    // class-major pixel mapping: (even,even)(even,odd)(odd,even)(odd,odd)
    int oy, ox;
    if (tid < 169)      { oy = 2 * (tid / 13);             ox = 2 * (tid % 13); }
    else if (tid < 325) { int t = tid - 169; oy = 2 * (t / 12);     ox = 2 * (t % 12) + 1; }
    else if (tid < 481) { int t = tid - 325; oy = 2 * (t / 13) + 1; ox = 2 * (t % 13); }
    else                { int t = tid - 481; oy = 2 * (t / 12) + 1; ox = 2 * (t % 12) + 1; }

    float4 acc[16];
#pragma unroll
    for (int c = 0; c < 16; c++) acc[c] = ((const float4*)bs)[c];
    int iys[2], kys[2], nys, ixs[2], kxs[2], nxs;
    if (oy & 1) { int m = (oy - 1) >> 1; iys[0] = m + 1; kys[0] = 0; iys[1] = m; kys[1] = 2; nys = 2; }
    else        { iys[0] = oy >> 1; kys[0] = 1; nys = 1; }
    if (ox & 1) { int m = (ox - 1) >> 1; ixs[0] = m + 1; kxs[0] = 0; ixs[1] = m; kxs[1] = 2; nxs = 2; }
    else        { ixs[0] = ox >> 1; kxs[0] = 1; nxs = 1; }
#pragma unroll 1
    for (int a = 0; a < nys; a++)
#pragma unroll 1
        for (int c = 0; c < nxs; c++) {
            const float* qp = qs + (iys[a] * 13 + ixs[c]) * 65;
            const float4* wp = (const float4*)(ws + (kys[a] * 3 + kxs[c]) * 64 * 64);
#pragma unroll 4
            for (int i = 0; i < 64; i++) {
                float hv = qp[i];
                const float4* w4 = wp + i * 16;
#pragma unroll
                for (int cc = 0; cc < 16; cc++) fma4(acc[cc], hv, w4[cc]);
            }
        }
    float4* out = (float4*)(g_d1 + ((size_t)b * 625 + oy * 25 + ox) * 64);
#pragma unroll
    for (int c = 0; c < 16; c++) {
        float4 v = acc[c];
        v.x = fmaxf(v.x, 0.f); v.y = fmaxf(v.y, 0.f);
        v.z = fmaxf(v.z, 0.f); v.w = fmaxf(v.w, 0.f);
        out[c] = v;
    }
}

// ------- K5: tconv2 (64->32, k3 s2 p1 op1, relu), 25 -> 50, d1 via L2 -------
#define T2_SMEM ((18432 + 32) * 4)
__global__ void __launch_bounds__(1024) k_tconv2(const float* __restrict__ w,
                                                 const float* __restrict__ bias) {
    extern __shared__ float sm[];
    float* ws = sm;               // [(t*64+i)*32 + o]
    float* bs = sm + 18432;
    int b = blockIdx.x, tid = threadIdx.x;
    for (int e = tid; e < 18432; e += 1024) {
        int o = e / 576, r = e % 576, i = r / 9, t = r % 9;
        ws[(t * 64 + i) * 32 + o] = w[e];
    }
    if (tid < 32) bs[tid] = bias[tid];
    __syncthreads();
    const float* d1b = g_d1 + (size_t)b * 625 * 64;
    for (int p = tid; p < 2500; p += 1024) {
        int cls = p / 625, r = p % 625;
        int oy = 2 * (r / 25) + (cls >> 1);
        int ox = 2 * (r % 25) + (cls & 1);
        float4 acc[8];
#pragma unroll
        for (int c = 0; c < 8; c++) acc[c] = ((const float4*)bs)[c];
        int iys[2], kys[2], nys = 0, ixs[2], kxs[2], nxs = 0;
        if (oy & 1) { int m = (oy - 1) >> 1;
            if (m + 1 < 25) { iys[nys] = m + 1; kys[nys] = 0; nys++; }
            iys[nys] = m; kys[nys] = 2; nys++;
        } else { iys[0] = oy >> 1; kys[0] = 1; nys = 1; }
        if (ox & 1) { int m = (ox - 1) >> 1;
            if (m + 1 < 25) { ixs[nxs] = m + 1; kxs[nxs] = 0; nxs++; }
            ixs[nxs] = m; kxs[nxs] = 2; nxs++;
        } else { ixs[0] = ox >> 1; kxs[0] = 1; nxs = 1; }
#pragma unroll 1
        for (int a = 0; a < nys; a++)
#pragma unroll 1
            for (int c = 0; c < nxs; c++) {
                const float4* xp = (const float4*)(d1b + (iys[a] * 25 + ixs[c]) * 64);
                const float4* wp = (const float4*)(ws + (kys[a] * 3 + kxs[c]) * 64 * 32);
#pragma unroll 4
                for (int i4 = 0; i4 < 16; i4++) {
                    float4 hv = __ldg(xp + i4);
                    const float4* w4 = wp + i4 * 32;
#pragma unroll
                    for (int cc = 0; cc < 8; cc++) fma4(acc[cc], hv.x, w4[cc]);
#pragma unroll
                    for (int cc = 0; cc < 8; cc++) fma4(acc[cc], hv.y, w4[8 + cc]);
#pragma unroll
                    for (int cc = 0; cc < 8; cc++) fma4(acc[cc], hv.z, w4[16 + cc]);
#pragma unroll
                    for (int cc = 0; cc < 8; cc++) fma4(acc[cc], hv.w, w4[24 + cc]);
                }
            }
        float4* out = (float4*)(g_d2 + ((size_t)b * 2500 + oy * 50 + ox) * 32);
#pragma unroll
        for (int c = 0; c < 8; c++) {
            float4 v = acc[c];
            v.x = fmaxf(v.x, 0.f); v.y = fmaxf(v.y, 0.f);
            v.z = fmaxf(v.z, 0.f); v.w = fmaxf(v.w, 0.f);
            out[c] = v;
        }
    }
}

// -------------- K6: conv (32->1, k3 s1 p1) + sigmoid ------------------------
__global__ void __launch_bounds__(1024) k_outconv(const float* __restrict__ w,
                                                  const float* __restrict__ bias,
                                                  float* __restrict__ out) {
    __shared__ float ws[288];  // [t*32 + i]
    __shared__ float b0;
    int b = blockIdx.x, tid = threadIdx.x;
    if (tid < 288) { int i = tid / 9, t = tid % 9; ws[t * 32 + i] = w[tid]; }
    if (tid == 0) b0 = bias[0];
    __syncthreads();
    const float* d2b = g_d2 + (size_t)b * 2500 * 32;
    for (int p = tid; p < 2500; p += 1024) {
        int oy = p / 50, ox = p % 50;
        float a = b0;
#pragma unroll
        for (int ky = 0; ky < 3; ky++) {
            int iy = oy + ky - 1;
            if (iy < 0 || iy >= 50) continue;
#pragma unroll
            for (int kx = 0; kx < 3; kx++) {
                int ix = ox + kx - 1;
                if (ix < 0 || ix >= 50) continue;
                const float4* xp = (const float4*)(d2b + (iy * 50 + ix) * 32);
                const float4* wp = (const float4*)(ws + (ky * 3 + kx) * 32);
#pragma unroll
                for (int i4 = 0; i4 < 8; i4++) {
                    float4 v = __ldg(xp + i4); float4 wv = wp[i4];
                    a = fmaf(v.x, wv.x, a); a = fmaf(v.y, wv.y, a);
                    a = fmaf(v.z, wv.z, a); a = fmaf(v.w, wv.w, a);
                }
            }
        }
        out[(size_t)b * 2500 + p] = 1.f / (1.f + __expf(-a));
    }
}

// ---------------------------------------------------------------------------
extern "C" void kernel_launch(void* const* d_in, const int* in_sizes, int n_in,
                              void* d_out, int out_size) {
    const float* x      = (const float*)d_in[0];
    const float* enc_w1 = (const float*)d_in[1];
    const float* enc_b1 = (const float*)d_in[2];
    const float* enc_w2 = (const float*)d_in[3];
    const float* enc_b2 = (const float*)d_in[4];
    const float* enc_w3 = (const float*)d_in[5];
    const float* enc_b3 = (const float*)d_in[6];
    const float* cb     = (const float*)d_in[7];
    const float* dec_w1 = (const float*)d_in[8];
    const float* dec_b1 = (const float*)d_in[9];
    const float* dec_w2 = (const float*)d_in[10];
    const float* dec_b2 = (const float*)d_in[11];
    const float* dec_w3 = (const float*)d_in[12];
    const float* dec_b3 = (const float*)d_in[13];
    float* out = (float*)d_out;

    cudaFuncSetAttribute(k_enc23,  cudaFuncAttributeMaxDynamicSharedMemorySize, ENC23_SMEM);
    cudaFuncSetAttribute(k_vq,     cudaFuncAttributeMaxDynamicSharedMemorySize, VQ_SMEM);
    cudaFuncSetAttribute(k_tconv1, cudaFuncAttributeMaxDynamicSharedMemorySize, T1_SMEM);
    cudaFuncSetAttribute(k_tconv2, cudaFuncAttributeMaxDynamicSharedMemorySize, T2_SMEM);

    // q scratch lives in g_d2 (consumed by k_tconv1 before k_tconv2 overwrites it)
    float* q = g_d2;

    k_conv1 <<<BATCH, 640>>>(x, enc_w1, enc_b1);
    k_enc23 <<<BATCH, 192, ENC23_SMEM>>>(enc_w2, enc_b2, enc_w3, enc_b3);
    k_cnorm <<<1, 512>>>(cb);
    k_vq    <<<2704, 256, VQ_SMEM>>>(cb, q);
    k_loss  <<<1, 256>>>(out + (out_size - 1));
    k_tconv1<<<BATCH, 640, T1_SMEM>>>(q, dec_w1, dec_b1);
    k_tconv2<<<BATCH, 1024, T2_SMEM>>>(dec_w2, dec_b2);
    k_outconv<<<BATCH, 1024>>>(dec_w3, dec_b3, out);
}

// round 11
// speedup vs baseline: 1.0165x; 1.0165x over previous
#include <cuda_runtime.h>
#include <cstdint>
#include <cstddef>

#define BATCH 1024

typedef unsigned long long ull;

__device__ __align__(256) float g_h1[BATCH * 32 * 625];     // (B,32,25,25) planar
__device__ __align__(256) float g_z [BATCH * 169 * 64];     // (B,169,64) pixel-major
__device__ __align__(256) float g_d1[BATCH * 625 * 64];     // (B,625,64) pixel-major
__device__ __align__(256) float g_d2[BATCH * 2500 * 32];    // (B,2500,32) pixel-major
__device__ __align__(256) float g_lsum[2704];
__device__ __align__(256) float g_cnorm[512];

// ---- packed f32x2 helpers (sm_103a FFMA2 pipe; ptxas never auto-emits) -----
__device__ __forceinline__ ull pk2(float a) {
    ull r; asm("mov.b64 %0,{%1,%1};" : "=l"(r) : "f"(a)); return r;
}
__device__ __forceinline__ void fma2(ull& d, ull a, ull b) {
    asm("fma.rn.f32x2 %0,%1,%2,%0;" : "+l"(d) : "l"(a), "l"(b));
}
__device__ __forceinline__ float2 up2(ull v) {
    float2 f; asm("mov.b64 {%0,%1},%2;" : "=f"(f.x), "=f"(f.y) : "l"(v)); return f;
}

// ---------------- K1: conv1 (1->32, k3 s2 p1, relu), 50->25 -----------------
__global__ void __launch_bounds__(640) k_conv1(const float* __restrict__ x,
                                               const float* __restrict__ w,
                                               const float* __restrict__ bias) {
    __shared__ float ws[288], bs[32];
    int b = blockIdx.x, tid = threadIdx.x;
    if (tid < 288) ws[tid] = w[tid];
    if (tid < 32)  bs[tid] = bias[tid];
    __syncthreads();
    if (tid >= 625) return;
    int oy = tid / 25, ox = tid % 25;
    const float* xb = x + (size_t)b * 2500;
    float xv[9];
#pragma unroll
    for (int ky = 0; ky < 3; ky++)
#pragma unroll
        for (int kx = 0; kx < 3; kx++) {
            int iy = 2 * oy + ky - 1, ix = 2 * ox + kx - 1;
            xv[ky * 3 + kx] = (iy >= 0 && iy < 50 && ix >= 0 && ix < 50) ? xb[iy * 50 + ix] : 0.f;
        }
    float* out = g_h1 + (size_t)b * 20000 + tid;
#pragma unroll
    for (int oc = 0; oc < 32; oc++) {
        float a = bs[oc];
#pragma unroll
        for (int t = 0; t < 9; t++) a = fmaf(xv[t], ws[oc * 9 + t], a);
        out[oc * 625] = fmaxf(a, 0.f);
    }
}

// ------------- K2: conv2 (32->64 k3 s2 p1 relu) + conv3 1x1 -> z ------------
#define ENC23_SMEM ((20000 + 18432 + 4096 + 64 + 64) * 4)
__global__ void __launch_bounds__(192) k_enc23(const float* __restrict__ w2,
                                               const float* __restrict__ b2,
                                               const float* __restrict__ w3,
                                               const float* __restrict__ b3) {
    extern __shared__ float sm[];
    float* h1s = sm;             // 20000 planar; later reused as h2 [169][65]
    float* w2s = sm + 20000;     // [ (t*32+i)*64 + o ]
    float* w3s = sm + 38432;     // [ k*64 + c ]
    float* b2s = sm + 42528;
    float* b3s = sm + 42592;
    int b = blockIdx.x, tid = threadIdx.x;
    const float* h1b = g_h1 + (size_t)b * 20000;
    for (int e = tid; e < 20000; e += 192) h1s[e] = h1b[e];
    for (int e = tid; e < 18432; e += 192) {
        int o = e / 288, r = e % 288, i = r / 9, t = r % 9;
        w2s[(t * 32 + i) * 64 + o] = w2[e];
    }
    for (int e = tid; e < 4096; e += 192) w3s[(e & 63) * 64 + (e >> 6)] = w3[e];
    if (tid < 64) { b2s[tid] = b2[tid]; b3s[tid] = b3[tid]; }
    __syncthreads();

    ull acc[32];
    if (tid < 169) {
        int oy = tid / 13, ox = tid % 13;
#pragma unroll
        for (int c = 0; c < 32; c++) acc[c] = ((const ull*)b2s)[c];
#pragma unroll 1
        for (int ky = 0; ky < 3; ky++) {
            int iy = 2 * oy + ky - 1;
            if (iy < 0 || iy >= 25) continue;
#pragma unroll 1
            for (int kx = 0; kx < 3; kx++) {
                int ix = 2 * ox + kx - 1;
                if (ix < 0 || ix >= 25) continue;
                const float* hp = h1s + iy * 25 + ix;
                const ulonglong2* wp = (const ulonglong2*)(w2s + (ky * 3 + kx) * 32 * 64);
#pragma unroll 4
                for (int i = 0; i < 32; i++) {
                    ull hv2 = pk2(hp[i * 625]);
                    const ulonglong2* w4 = wp + i * 16;
#pragma unroll
                    for (int cc = 0; cc < 16; cc++) {
                        ulonglong2 wv = w4[cc];
                        fma2(acc[2 * cc], hv2, wv.x);
                        fma2(acc[2 * cc + 1], hv2, wv.y);
                    }
                }
            }
        }
    }
    __syncthreads();
    if (tid < 169) {
        float* hrow = h1s + tid * 65;
#pragma unroll
        for (int c = 0; c < 32; c++) {
            float2 v = up2(acc[c]);
            hrow[2 * c]     = fmaxf(v.x, 0.f);
            hrow[2 * c + 1] = fmaxf(v.y, 0.f);
        }
    }
    __syncthreads();
    if (tid < 169) {
        ull za[32];
#pragma unroll
        for (int c = 0; c < 32; c++) za[c] = ((const ull*)b3s)[c];
        const float* hp = h1s + tid * 65;
#pragma unroll 4
        for (int k = 0; k < 64; k++) {
            ull hv2 = pk2(hp[k]);
            const ulonglong2* w4 = (const ulonglong2*)(w3s + k * 64);
#pragma unroll
            for (int cc = 0; cc < 16; cc++) {
                ulonglong2 wv = w4[cc];
                fma2(za[2 * cc], hv2, wv.x);
                fma2(za[2 * cc + 1], hv2, wv.y);
            }
        }
        ull* zp = (ull*)(g_z + ((size_t)b * 169 + tid) * 64);
#pragma unroll
        for (int c = 0; c < 32; c++) zp[c] = za[c];
    }
}

// ---------------- K3a: codebook row norms -----------------------------------
__global__ void k_cnorm(const float* __restrict__ cb) {
    const float* r = cb + threadIdx.x * 64;
    float s = 0.f;
#pragma unroll
    for (int k = 0; k < 64; k++) s = fmaf(r[k], r[k], s);
    g_cnorm[threadIdx.x] = s;
}

// -------- K3: VQ. 64 pixels x 512 codes per block, reg tile, f32x2 ----------
// thread tx handles code pairs {2tx+64jp, 2tx+64jp+1}, jp=0..3, two passes.
#define VQ_SMEM ((4096 + 64 * 258 + 8) * 4)
__global__ void __launch_bounds__(256) k_vq(const float* __restrict__ cb,
                                            float* __restrict__ q) {
    extern __shared__ float sm[];
    float* zs = sm;               // [64][64]
    float* cs = sm + 4096;        // [64][258] k-major padded (8B-aligned pairs)
    float* sred = sm + 4096 + 64 * 258;
    int tid = threadIdx.x;
    int P0 = blockIdx.x * 64;
    {
        const float4* zsrc = (const float4*)(g_z + (size_t)P0 * 64);
        float4* zd = (float4*)zs;
        for (int e = tid; e < 1024; e += 256) zd[e] = zsrc[e];
    }
    int ty = tid >> 5, tx = tid & 31;
    float bestd[8]; int besti[8];
#pragma unroll
    for (int i = 0; i < 8; i++) { bestd[i] = 3.4e38f; besti[i] = 0; }

    for (int pass = 0; pass < 2; pass++) {
        int C0 = pass * 256;
        __syncthreads();
        for (int e = tid; e < 16384; e += 256) {
            int code = e >> 6, k = e & 63;
            cs[k * 258 + code] = cb[(C0 + code) * 64 + k];
        }
        __syncthreads();
        ull dot2[8][4];
#pragma unroll
        for (int i = 0; i < 8; i++)
#pragma unroll
            for (int jp = 0; jp < 4; jp++) dot2[i][jp] = 0ull;
        const float* zrow = zs + (ty * 8) * 64;
#pragma unroll 2
        for (int k = 0; k < 64; k++) {
            ull zf2[8], cf2[4];
#pragma unroll
            for (int i = 0; i < 8; i++) zf2[i] = pk2(zrow[i * 64 + k]);
            const ull* crow = (const ull*)(cs + k * 258 + 2 * tx);
#pragma unroll
            for (int jp = 0; jp < 4; jp++) cf2[jp] = crow[jp * 32];
#pragma unroll
            for (int i = 0; i < 8; i++)
#pragma unroll
                for (int jp = 0; jp < 4; jp++) fma2(dot2[i][jp], zf2[i], cf2[jp]);
        }
#pragma unroll
        for (int jp = 0; jp < 4; jp++) {
            int ci0 = C0 + 2 * tx + 64 * jp;
            float cn0 = __ldg(g_cnorm + ci0);
            float cn1 = __ldg(g_cnorm + ci0 + 1);
#pragma unroll
            for (int i = 0; i < 8; i++) {
                float2 dd = up2(dot2[i][jp]);
                float d0 = fmaf(-2.f, dd.x, cn0);
                float d1 = fmaf(-2.f, dd.y, cn1);
                if (d0 < bestd[i]) { bestd[i] = d0; besti[i] = ci0; }
                if (d1 < bestd[i]) { bestd[i] = d1; besti[i] = ci0 + 1; }
            }
        }
    }
#pragma unroll
    for (int i = 0; i < 8; i++) {
        float d = bestd[i]; int ci = besti[i];
#pragma unroll
        for (int off = 16; off; off >>= 1) {
            float od = __shfl_xor_sync(0xffffffffu, d, off);
            int   oi = __shfl_xor_sync(0xffffffffu, ci, off);
            if (od < d || (od == d && oi < ci)) { d = od; ci = oi; }
        }
        besti[i] = ci;
    }
    float ls = 0.f;
#pragma unroll
    for (int i = 0; i < 8; i++) {
        int p = ty * 8 + i, ci = besti[i];
        float c0 = __ldg(cb + ci * 64 + tx);
        float c1 = __ldg(cb + ci * 64 + 32 + tx);
        float z0 = zs[p * 64 + tx], z1 = zs[p * 64 + 32 + tx];
        float* qp = q + ((size_t)(P0 + p)) * 64;
        qp[tx] = c0; qp[32 + tx] = c1;
        float d0 = c0 - z0, d1 = c1 - z1;
        ls = fmaf(d0, d0, ls); ls = fmaf(d1, d1, ls);
    }
#pragma unroll
    for (int off = 16; off; off >>= 1) ls += __shfl_xor_sync(0xffffffffu, ls, off);
    if (tx == 0) sred[ty] = ls;
    __syncthreads();
    if (tid == 0) {
        float s = 0.f;
        for (int w = 0; w < 8; w++) s += sred[w];
        g_lsum[blockIdx.x] = s;
    }
}

// loss = 1.25 * sum / (1024*64*169)
__global__ void k_loss(float* __restrict__ out) {
    __shared__ float s[256];
    float a = 0.f;
    for (int e = threadIdx.x; e < 2704; e += 256) a += g_lsum[e];
    s[threadIdx.x] = a;
    __syncthreads();
    for (int st = 128; st; st >>= 1) {
        if (threadIdx.x < st) s[threadIdx.x] += s[threadIdx.x + st];
        __syncthreads();
    }
    if (threadIdx.x == 0) out[0] = s[0] * (1.25f / 11075584.f);
}

// ------- K4: tconv1 (64->64, k3 s2 p1 op0, relu), 13 -> 25, smem-staged -----
#define T1_SMEM ((10988 + 36864 + 64) * 4)
__global__ void __launch_bounds__(640) k_tconv1(const float* __restrict__ q,
                                                const float* __restrict__ w,
                                                const float* __restrict__ bias) {
    extern __shared__ float sm[];
    float* qs = sm;               // [169][65] (scalar reads only)
    float* ws = sm + 10988;       // [(t*64+i)*64 + o], 16B-aligned
    float* bs = sm + 10988 + 36864;
    int b = blockIdx.x, tid = threadIdx.x;
    const float* qb = q + (size_t)b * 169 * 64;
    for (int e = tid; e < 169 * 64; e += 640) qs[(e >> 6) * 65 + (e & 63)] = qb[e];
    for (int e = tid; e < 36864; e += 640) {
        int o = e / 576, r = e % 576, i = r / 9, t = r % 9;
        ws[(t * 64 + i) * 64 + o] = w[e];
    }
    if (tid < 64) bs[tid] = bias[tid];
    __syncthreads();
    if (tid >= 625) return;
    int oy, ox;
    if (tid < 169)      { oy = 2 * (tid / 13);             ox = 2 * (tid % 13); }
    else if (tid < 325) { int t = tid - 169; oy = 2 * (t / 12);     ox = 2 * (t % 12) + 1; }
    else if (tid < 481) { int t = tid - 325; oy = 2 * (t / 13) + 1; ox = 2 * (t % 13); }
    else                { int t = tid - 481; oy = 2 * (t / 12) + 1; ox = 2 * (t % 12) + 1; }

    ull acc[32];
#pragma unroll
    for (int c = 0; c < 32; c++) acc[c] = ((const ull*)bs)[c];
    int iys[2], kys[2], nys, ixs[2], kxs[2], nxs;
    if (oy & 1) { int m = (oy - 1) >> 1; iys[0] = m + 1; kys[0] = 0; iys[1] = m; kys[1] = 2; nys = 2; }
    else        { iys[0] = oy >> 1; kys[0] = 1; nys = 1; }
    if (ox & 1) { int m = (ox - 1) >> 1; ixs[0] = m + 1; kxs[0] = 0; ixs[1] = m; kxs[1] = 2; nxs = 2; }
    else        { ixs[0] = ox >> 1; kxs[0] = 1; nxs = 1; }
#pragma unroll 1
    for (int a = 0; a < nys; a++)
#pragma unroll 1
        for (int c = 0; c < nxs; c++) {
            const float* qp = qs + (iys[a] * 13 + ixs[c]) * 65;
            const ulonglong2* wp = (const ulonglong2*)(ws + (kys[a] * 3 + kxs[c]) * 64 * 64);
#pragma unroll 4
            for (int i = 0; i < 64; i++) {
                ull hv2 = pk2(qp[i]);
                const ulonglong2* w4 = wp + i * 16;
#pragma unroll
                for (int cc = 0; cc < 16; cc++) {
                    ulonglong2 wv = w4[cc];
                    fma2(acc[2 * cc], hv2, wv.x);
                    fma2(acc[2 * cc + 1], hv2, wv.y);
                }
            }
        }
    float* out = g_d1 + ((size_t)b * 625 + oy * 25 + ox) * 64;
#pragma unroll
    for (int c = 0; c < 32; c++) {
        float2 v = up2(acc[c]);
        out[2 * c]     = fmaxf(v.x, 0.f);
        out[2 * c + 1] = fmaxf(v.y, 0.f);
    }
}

// ------- K5: tconv2 (64->32, k3 s2 p1 op1, relu), 25 -> 50, d1 via L2 -------
#define T2_SMEM ((18432 + 32) * 4)
__global__ void __launch_bounds__(1024) k_tconv2(const float* __restrict__ w,
                                                 const float* __restrict__ bias) {
    extern __shared__ float sm[];
    float* ws = sm;               // [(t*64+i)*32 + o]
    float* bs = sm + 18432;
    int b = blockIdx.x, tid = threadIdx.x;
    for (int e = tid; e < 18432; e += 1024) {
        int o = e / 576, r = e % 576, i = r / 9, t = r % 9;
        ws[(t * 64 + i) * 32 + o] = w[e];
    }
    if (tid < 32) bs[tid] = bias[tid];
    __syncthreads();
    const float* d1b = g_d1 + (size_t)b * 625 * 64;
    for (int p = tid; p < 2500; p += 1024) {
        int cls = p / 625, r = p % 625;
        int oy = 2 * (r / 25) + (cls >> 1);
        int ox = 2 * (r % 25) + (cls & 1);
        ull acc[16];
#pragma unroll
        for (int c = 0; c < 16; c++) acc[c] = ((const ull*)bs)[c];
        int iys[2], kys[2], nys = 0, ixs[2], kxs[2], nxs = 0;
        if (oy & 1) { int m = (oy - 1) >> 1;
            if (m + 1 < 25) { iys[nys] = m + 1; kys[nys] = 0; nys++; }
            iys[nys] = m; kys[nys] = 2; nys++;
        } else { iys[0] = oy >> 1; kys[0] = 1; nys = 1; }
        if (ox & 1) { int m = (ox - 1) >> 1;
            if (m + 1 < 25) { ixs[nxs] = m + 1; kxs[nxs] = 0; nxs++; }
            ixs[nxs] = m; kxs[nxs] = 2; nxs++;
        } else { ixs[0] = ox >> 1; kxs[0] = 1; nxs = 1; }
#pragma unroll 1
        for (int a = 0; a < nys; a++)
#pragma unroll 1
            for (int c = 0; c < nxs; c++) {
                const float4* xp = (const float4*)(d1b + (iys[a] * 25 + ixs[c]) * 64);
                const float* wbase = ws + (kys[a] * 3 + kxs[c]) * 64 * 32;
#pragma unroll 4
                for (int i4 = 0; i4 < 16; i4++) {
                    float4 hv = __ldg(xp + i4);
                    ull h[4] = { pk2(hv.x), pk2(hv.y), pk2(hv.z), pk2(hv.w) };
#pragma unroll
                    for (int ic = 0; ic < 4; ic++) {
                        const ulonglong2* w4 = (const ulonglong2*)(wbase + (i4 * 4 + ic) * 32);
#pragma unroll
                        for (int cc = 0; cc < 8; cc++) {
                            ulonglong2 wv = w4[cc];
                            fma2(acc[2 * cc],     h[ic], wv.x);
                            fma2(acc[2 * cc + 1], h[ic], wv.y);
                        }
                    }
                }
            }
        float* out = g_d2 + ((size_t)b * 2500 + oy * 50 + ox) * 32;
#pragma unroll
        for (int c = 0; c < 16; c++) {
            float2 v = up2(acc[c]);
            out[2 * c]     = fmaxf(v.x, 0.f);
            out[2 * c + 1] = fmaxf(v.y, 0.f);
        }
    }
}

// -------------- K6: conv (32->1, k3 s1 p1) + sigmoid, f32x2 -----------------
__global__ void __launch_bounds__(1024) k_outconv(const float* __restrict__ w,
                                                  const float* __restrict__ bias,
                                                  float* __restrict__ out) {
    __shared__ float ws[288];  // [t*32 + i]
    __shared__ float b0;
    int b = blockIdx.x, tid = threadIdx.x;
    if (tid < 288) { int i = tid / 9, t = tid % 9; ws[t * 32 + i] = w[tid]; }
    if (tid == 0) b0 = bias[0];
    __syncthreads();
    const float* d2b = g_d2 + (size_t)b * 2500 * 32;
    for (int p = tid; p < 2500; p += 1024) {
        int oy = p / 50, ox = p % 50;
        ull accA = 0ull, accB = 0ull;
#pragma unroll
        for (int ky = 0; ky < 3; ky++) {
            int iy = oy + ky - 1;
            if (iy < 0 || iy >= 50) continue;
#pragma unroll
            for (int kx = 0; kx < 3; kx++) {
                int ix = ox + kx - 1;
                if (ix < 0 || ix >= 50) continue;
                const ulonglong2* xp = (const ulonglong2*)(d2b + (iy * 50 + ix) * 32);
                const ulonglong2* wp = (const ulonglong2*)(ws + (ky * 3 + kx) * 32);
#pragma unroll
                for (int i4 = 0; i4 < 8; i4++) {
                    ulonglong2 xv = __ldg(xp + i4);
                    ulonglong2 wv = wp[i4];
                    fma2(accA, xv.x, wv.x);
                    fma2(accB, xv.y, wv.y);
                }
            }
        }
        float2 fa = up2(accA), fb = up2(accB);
        float a = b0 + ((fa.x + fa.y) + (fb.x + fb.y));
        out[(size_t)b * 2500 + p] = 1.f / (1.f + __expf(-a));
    }
}

// ---------------------------------------------------------------------------
extern "C" void kernel_launch(void* const* d_in, const int* in_sizes, int n_in,
                              void* d_out, int out_size) {
    const float* x      = (const float*)d_in[0];
    const float* enc_w1 = (const float*)d_in[1];
    const float* enc_b1 = (const float*)d_in[2];
    const float* enc_w2 = (const float*)d_in[3];
    const float* enc_b2 = (const float*)d_in[4];
    const float* enc_w3 = (const float*)d_in[5];
    const float* enc_b3 = (const float*)d_in[6];
    const float* cb     = (const float*)d_in[7];
    const float* dec_w1 = (const float*)d_in[8];
    const float* dec_b1 = (const float*)d_in[9];
    const float* dec_w2 = (const float*)d_in[10];
    const float* dec_b2 = (const float*)d_in[11];
    const float* dec_w3 = (const float*)d_in[12];
    const float* dec_b3 = (const float*)d_in[13];
    float* out = (float*)d_out;

    cudaFuncSetAttribute(k_enc23,  cudaFuncAttributeMaxDynamicSharedMemorySize, ENC23_SMEM);
    cudaFuncSetAttribute(k_vq,     cudaFuncAttributeMaxDynamicSharedMemorySize, VQ_SMEM);
    cudaFuncSetAttribute(k_tconv1, cudaFuncAttributeMaxDynamicSharedMemorySize, T1_SMEM);
    cudaFuncSetAttribute(k_tconv2, cudaFuncAttributeMaxDynamicSharedMemorySize, T2_SMEM);

    // q scratch lives in g_d2 (consumed by k_tconv1 before k_tconv2 overwrites it)
    float* q = g_d2;

    k_conv1 <<<BATCH, 640>>>(x, enc_w1, enc_b1);
    k_enc23 <<<BATCH, 192, ENC23_SMEM>>>(enc_w2, enc_b2, enc_w3, enc_b3);
    k_cnorm <<<1, 512>>>(cb);
    k_vq    <<<2704, 256, VQ_SMEM>>>(cb, q);
    k_loss  <<<1, 256>>>(out + (out_size - 1));
    k_tconv1<<<BATCH, 640, T1_SMEM>>>(q, dec_w1, dec_b1);
    k_tconv2<<<BATCH, 1024, T2_SMEM>>>(dec_w2, dec_b2);
    k_outconv<<<BATCH, 1024>>>(dec_w3, dec_b3, out);
}